// round 2
// baseline (speedup 1.0000x reference)
#include <cuda_runtime.h>
#include <math.h>

// Problem constants (fixed by setup_inputs)
#define LMAXC 180
#define LC    181           // L = lmax+1
#define MMC   361           // 2*lmax+1
#define FC    50            // n_freqs
#define NCC   100           // 2*F real columns (re/im interleaved)
#define NCPC  104           // padded smem width
#define TMC   32            // m-tile
#define KCC   32            // k-chunk
#define NTHREADS 128
#define SIDEREALF 6.3003880989848976f   // 2*pi*1.00273790935 (fp32 of double)
#define SQRT4PI   3.5449077018110318f

// Scratch (no allocations allowed): S[m][2f] accumulator + per-freq norm
__device__ float g_S[MMC * NCC];
__device__ float g_norm[FC];

__global__ void zero_S() {
    int i = blockIdx.x * blockDim.x + threadIdx.x;
    if (i < MMC * NCC) g_S[i] = 0.0f;
}

// Per (l, m-tile) CTA:
//   D[m,f] = sum_n dl[l,m,n] * conj(beam[f,l,n]*pg[n])     (real GEMM, 2F cols)
//   S[m,f] += conj(pa[m]) * D[m,f] * sky[f,l,m]            (valid (l,m) only)
// l==0 CTA also writes g_norm[f] = sqrt(4pi)*Re(D[m=0,f]).
__global__ void __launch_bounds__(NTHREADS) conv_kernel(
    const float* __restrict__ br_g, const float* __restrict__ bi_g,
    const float* __restrict__ sr_g, const float* __restrict__ si_g,
    const float* __restrict__ dl_g, const float* __restrict__ euler)
{
    const int l  = blockIdx.y;
    const int j0 = LMAXC - l, j1 = LMAXC + l;
    const int ntiles = (2 * l + 1 + TMC - 1) / TMC;
    const int mt = blockIdx.x;
    if (mt >= ntiles) return;
    const int jm0 = j0 + mt * TMC;

    const float alpha = euler[0];
    const float gamma = euler[2];

    __shared__ float a_sm[TMC][KCC + 1];
    __shared__ float b_sm[KCC][NCPC];
    __shared__ float pgc[KCC], pgs[KCC];

    const int tid = threadIdx.x;
    const int r   = tid >> 2;      // 32 m-rows
    const int cg  = tid & 3;       // 4 column groups
    const int cbase = cg * 26;     // 26 cols per thread (cols 100..103 are padding)

    float acc[26];
    #pragma unroll
    for (int c = 0; c < 26; c++) acc[c] = 0.0f;

    for (int k0 = j0; k0 <= j1; k0 += KCC) {
        __syncthreads();  // previous compute done before overwriting tiles

        // dl tile: rows jm0..jm0+31, cols k0..k0+31 (coalesced 128B rows)
        for (int i = tid; i < TMC * KCC; i += NTHREADS) {
            int rr = i >> 5, cc = i & 31;
            int jj = jm0 + rr, nn = k0 + cc;
            float v = 0.0f;
            if (jj <= j1 && nn <= j1)
                v = dl_g[((size_t)l * MMC + jj) * MMC + nn];
            a_sm[rr][cc] = v;
        }
        // pg phases for this k-chunk
        if (tid < KCC) {
            int nn = k0 + tid;
            float s = 0.0f, c = 0.0f;
            if (nn <= j1) sincosf((float)(nn - LMAXC) * gamma, &s, &c);
            pgc[tid] = c; pgs[tid] = s;
        }
        __syncthreads();

        // B tile: conj(beam * pg), re/im as separate columns
        for (int i = tid; i < KCC * FC; i += NTHREADS) {
            int nl = i & 31, f = i >> 5;
            int nn = k0 + nl;
            float brv = 0.0f, biv = 0.0f;
            if (nn <= j1) {
                size_t off = ((size_t)f * LC + l) * MMC + nn;
                brv = br_g[off]; biv = bi_g[off];
            }
            float c = pgc[nl], s = pgs[nl];
            b_sm[nl][2 * f]     = brv * c + biv * s;   // Re(conj(beam*pg))
            b_sm[nl][2 * f + 1] = brv * s - biv * c;   // Im(conj(beam*pg))
        }
        if (tid < KCC) {  // zero the padding columns read by cg==3
            b_sm[tid][100] = 0.f; b_sm[tid][101] = 0.f;
            b_sm[tid][102] = 0.f; b_sm[tid][103] = 0.f;
        }
        __syncthreads();

        const int kmax = min(KCC, j1 - k0 + 1);
        for (int k = 0; k < kmax; k++) {
            float a = a_sm[r][k];
            const float2* bp = reinterpret_cast<const float2*>(&b_sm[k][cbase]);
            #pragma unroll
            for (int c2 = 0; c2 < 13; c2++) {
                float2 b = bp[c2];
                acc[2 * c2]     += a * b.x;
                acc[2 * c2 + 1] += a * b.y;
            }
        }
    }

    const int jrow = jm0 + r;
    if (jrow <= j1) {
        float sa, ca;  // conj(pa[m]) = exp(+i m alpha)
        sincosf((float)(jrow - LMAXC) * alpha, &sa, &ca);
        #pragma unroll
        for (int p = 0; p < 13; p++) {
            int f = cg * 13 + p;
            if (f < FC) {
                float dre = acc[2 * p], dim = acc[2 * p + 1];
                float z1r = ca * dre - sa * dim;
                float z1i = ca * dim + sa * dre;
                size_t soff = ((size_t)f * LC + l) * MMC + jrow;
                float skr = sr_g[soff], ski = si_g[soff];
                atomicAdd(&g_S[jrow * NCC + 2 * f],     z1r * skr - z1i * ski);
                atomicAdd(&g_S[jrow * NCC + 2 * f + 1], z1r * ski + z1i * skr);
            }
        }
        if (l == 0) {   // jrow==LMAXC here; pa[0]=1, Re(D)=Re(beam_eq[f,0,0])
            #pragma unroll
            for (int p = 0; p < 13; p++) {
                int f = cg * 13 + p;
                if (f < FC) g_norm[f] = SQRT4PI * acc[2 * p];
            }
        }
    }
}

// Per-time block: build e^{i m phi_t} table, contract with S, normalize, ground mix.
__global__ void vis_kernel(const float* __restrict__ times,
                           const float* __restrict__ fsky,
                           const float* __restrict__ tg,
                           float* __restrict__ out)
{
    const int t = blockIdx.x;
    __shared__ float phc[MMC], phs[MMC];
    float phi = SIDEREALF * times[t];
    for (int j = threadIdx.x; j < MMC; j += blockDim.x) {
        float s, c;
        sincosf((float)(j - LMAXC) * phi, &s, &c);
        phc[j] = c; phs[j] = s;
    }
    __syncthreads();
    int f = threadIdx.x;
    if (f < FC) {
        float acc = 0.0f;
        #pragma unroll 4
        for (int j = 0; j < MMC; j++) {
            acc += phc[j] * g_S[j * NCC + 2 * f]
                 - phs[j] * g_S[j * NCC + 2 * f + 1];
        }
        float v  = acc / g_norm[f];
        float fs = fsky[f];
        out[t * FC + f] = fs * v + (1.0f - fs) * 300.0f * tg[0];
    }
}

extern "C" void kernel_launch(void* const* d_in, const int* in_sizes, int n_in,
                              void* d_out, int out_size)
{
    const float* br    = (const float*)d_in[0];
    const float* bi    = (const float*)d_in[1];
    const float* sr    = (const float*)d_in[2];
    const float* si    = (const float*)d_in[3];
    const float* dl    = (const float*)d_in[4];
    const float* euler = (const float*)d_in[5];
    const float* times = (const float*)d_in[6];
    const float* fsky  = (const float*)d_in[7];
    const float* tg    = (const float*)d_in[8];
    float* out = (float*)d_out;
    const int T = in_sizes[6];

    zero_S<<<(MMC * NCC + 255) / 256, 256>>>();

    dim3 grid((MMC + TMC - 1) / TMC, LC);
    conv_kernel<<<grid, NTHREADS>>>(br, bi, sr, si, dl, euler);

    vis_kernel<<<T, 128>>>(times, fsky, tg, out);
}

// round 5
// speedup vs baseline: 1.6134x; 1.6134x over previous
#include <cuda_runtime.h>
#include <math.h>

// Problem constants (fixed by setup_inputs)
#define LMAXC 180
#define LC    181           // L = lmax+1
#define MMC   361           // 2*lmax+1
#define FC    50            // n_freqs
#define NCC   100           // 2*F real columns (re/im interleaved)
#define MT    64            // m-tile per CTA
#define KC    32            // k-chunk
#define ASTR  36            // A smem row stride (conflict-free frag loads)
#define BSTR  105           // B smem row stride
#define NTHREADS 256
#define SIDEREALF 6.3003880989848976f
#define SQRT4PI   3.5449077018110318f

// Scratch: S[m][2f] accumulator + per-freq norm (no allocations allowed)
__device__ float g_S[MMC * NCC];
__device__ float g_norm[FC];

__global__ void zero_S() {
    int i = blockIdx.x * blockDim.x + threadIdx.x;
    if (i < MMC * NCC) g_S[i] = 0.0f;
}

// tf32 split: v ~= hi + lo, both representable in tf32
__device__ __forceinline__ void split_tf32(float v, float& hi, float& lo) {
    unsigned uh;
    asm("cvt.rna.tf32.f32 %0, %1;" : "=r"(uh) : "f"(v));
    float hf = __uint_as_float(uh);
    float lf = v - hf;
    unsigned ul;
    asm("cvt.rna.tf32.f32 %0, %1;" : "=r"(ul) : "f"(lf));
    hi = hf; lo = __uint_as_float(ul);
}

__device__ __forceinline__ void mma_tf32(float* c,
    unsigned a0, unsigned a1, unsigned a2, unsigned a3,
    unsigned b0, unsigned b1)
{
    asm volatile(
        "mma.sync.aligned.m16n8k8.row.col.f32.tf32.tf32.f32 "
        "{%0,%1,%2,%3}, {%4,%5,%6,%7}, {%8,%9}, {%0,%1,%2,%3};"
        : "+f"(c[0]), "+f"(c[1]), "+f"(c[2]), "+f"(c[3])
        : "r"(a0), "r"(a1), "r"(a2), "r"(a3), "r"(b0), "r"(b1));
}

// Per (m-tile, l) CTA: tensor-core banded GEMM
//   D[m, 2f] = sum_n dl[l,m,n] * conj(beam[f,l,n] * pg[n])
// then epilogue S[m,f] += conj(pa[m]) * D[m,f] * sky[f,l,m]; l==0 also writes norm.
__global__ void __launch_bounds__(NTHREADS) conv_kernel(
    const float* __restrict__ br_g, const float* __restrict__ bi_g,
    const float* __restrict__ sr_g, const float* __restrict__ si_g,
    const float* __restrict__ dl_g, const float* __restrict__ euler)
{
    const int l  = blockIdx.y;
    const int j0 = LMAXC - l, j1 = LMAXC + l;
    const int W  = 2 * l + 1;
    const int ntiles = (W + MT - 1) / MT;
    const int mt = blockIdx.x;
    if (mt >= ntiles) return;
    const int jm0 = j0 + mt * MT;

    const float alpha = euler[0];
    const float gamma = euler[2];

    __shared__ float Ah[MT][ASTR], Al[MT][ASTR];      // dl tile hi/lo
    __shared__ float Bh[KC][BSTR], Bl[KC][BSTR];      // conj(beam*pg) tile hi/lo
    __shared__ float pgc[MMC], pgs[MMC];              // gamma phases, full band

    const int tid  = threadIdx.x;
    const int lane = tid & 31;
    const int warp = tid >> 5;
    const int mstrip = warp & 3;         // 4 strips of 16 m-rows
    const int nhalf  = warp >> 2;        // 0 -> n-tiles 0..6, 1 -> 7..12
    const int ntile0  = nhalf ? 7 : 0;
    const int ntcount = nhalf ? 6 : 7;

    // gamma phase table for the whole m-range (computed once)
    for (int j = tid; j < MMC; j += NTHREADS) {
        float s, c;
        sincosf((float)(j - LMAXC) * gamma, &s, &c);
        pgc[j] = c; pgs[j] = s;
    }
    __syncthreads();

    float acc[7][4];
    #pragma unroll
    for (int t = 0; t < 7; t++)
        #pragma unroll
        for (int q = 0; q < 4; q++) acc[t][q] = 0.0f;

    for (int k0 = j0; k0 <= j1; k0 += KC) {
        // ---- stage A: dl rows jm0..jm0+63, cols k0..k0+31, split hi/lo ----
        for (int i = tid; i < MT * KC; i += NTHREADS) {
            int rr = i >> 5, cc = i & 31;
            int jj = jm0 + rr, nn = k0 + cc;
            float v = 0.0f;
            if (jj <= j1 && nn <= j1)
                v = dl_g[((size_t)l * MMC + jj) * MMC + nn];
            float h, lo;
            split_tf32(v, h, lo);
            Ah[rr][cc] = h; Al[rr][cc] = lo;
        }
        // ---- stage B: conj(beam*pg), re/im columns, split hi/lo ----
        for (int i = tid; i < KC * 52; i += NTHREADS) {
            int nl = i & 31, f = i >> 5;     // coalesced over nl
            int nn = k0 + nl;
            float brv = 0.0f, biv = 0.0f;
            if (f < FC && nn <= j1) {
                size_t off = ((size_t)f * LC + l) * MMC + nn;
                brv = br_g[off]; biv = bi_g[off];
            }
            // OOB fix: clamp phase index (out-of-band lanes have brv=biv=0)
            int nnc = min(nn, 2 * LMAXC);
            float c = pgc[nnc], s = pgs[nnc];
            float re = brv * c + biv * s;    // Re(conj(beam*pg))
            float im = brv * s - biv * c;    // Im(conj(beam*pg))
            int col = 2 * f;                  // f>=50 lands in pad cols 100..103
            float h, lo;
            split_tf32(re, h, lo); Bh[nl][col] = h;     Bl[nl][col] = lo;
            split_tf32(im, h, lo); Bh[nl][col + 1] = h; Bl[nl][col + 1] = lo;
        }
        __syncthreads();

        // ---- MMA: 4 k-steps of 8 ----
        #pragma unroll
        for (int ks = 0; ks < 4; ks++) {
            const int kk = ks * 8;
            const int ar = mstrip * 16 + (lane >> 2);
            const int ac = kk + (lane & 3);
            unsigned a0h = __float_as_uint(Ah[ar][ac]);
            unsigned a1h = __float_as_uint(Ah[ar + 8][ac]);
            unsigned a2h = __float_as_uint(Ah[ar][ac + 4]);
            unsigned a3h = __float_as_uint(Ah[ar + 8][ac + 4]);
            unsigned a0l = __float_as_uint(Al[ar][ac]);
            unsigned a1l = __float_as_uint(Al[ar + 8][ac]);
            unsigned a2l = __float_as_uint(Al[ar][ac + 4]);
            unsigned a3l = __float_as_uint(Al[ar + 8][ac + 4]);
            const int bk = kk + (lane & 3);
            const int bc = lane >> 2;
            #pragma unroll
            for (int t = 0; t < 7; t++) {
                if (t < ntcount) {
                    int n0 = (ntile0 + t) * 8;
                    unsigned b0h = __float_as_uint(Bh[bk][n0 + bc]);
                    unsigned b1h = __float_as_uint(Bh[bk + 4][n0 + bc]);
                    unsigned b0l = __float_as_uint(Bl[bk][n0 + bc]);
                    unsigned b1l = __float_as_uint(Bl[bk + 4][n0 + bc]);
                    mma_tf32(acc[t], a0h, a1h, a2h, a3h, b0h, b1h);
                    mma_tf32(acc[t], a0h, a1h, a2h, a3h, b0l, b1l);
                    mma_tf32(acc[t], a0l, a1l, a2l, a3l, b0h, b1h);
                }
            }
        }
        __syncthreads();   // protect smem before next chunk's writes
    }

    // ---- epilogue: S[m,f] += conj(pa[m]) * D * sky ----
    const int r0 = jm0 + mstrip * 16 + (lane >> 2);
    const int r1 = r0 + 8;
    float sa0, ca0, sa1, ca1;
    sincosf((float)(r0 - LMAXC) * alpha, &sa0, &ca0);
    sincosf((float)(r1 - LMAXC) * alpha, &sa1, &ca1);
    const bool v0 = (r0 <= j1);
    const bool v1 = (r1 <= j1);

    #pragma unroll
    for (int t = 0; t < 7; t++) {
        if (t < ntcount) {
            int f = 4 * (ntile0 + t) + (lane & 3);
            if (f < FC) {
                if (v0) {
                    float dre = acc[t][0], dim = acc[t][1];
                    float z1r = ca0 * dre - sa0 * dim;
                    float z1i = ca0 * dim + sa0 * dre;
                    size_t soff = ((size_t)f * LC + l) * MMC + r0;
                    float skr = sr_g[soff], ski = si_g[soff];
                    atomicAdd(&g_S[r0 * NCC + 2 * f],     z1r * skr - z1i * ski);
                    atomicAdd(&g_S[r0 * NCC + 2 * f + 1], z1r * ski + z1i * skr);
                }
                if (v1) {
                    float dre = acc[t][2], dim = acc[t][3];
                    float z1r = ca1 * dre - sa1 * dim;
                    float z1i = ca1 * dim + sa1 * dre;
                    size_t soff = ((size_t)f * LC + l) * MMC + r1;
                    float skr = sr_g[soff], ski = si_g[soff];
                    atomicAdd(&g_S[r1 * NCC + 2 * f],     z1r * skr - z1i * ski);
                    atomicAdd(&g_S[r1 * NCC + 2 * f + 1], z1r * ski + z1i * skr);
                }
                if (l == 0 && mstrip == 0 && (lane >> 2) == 0) {
                    // r0 == LMAXC, pa = 1: norm = sqrt(4pi) * Re(D)
                    g_norm[f] = SQRT4PI * acc[t][0];
                }
            }
        }
    }
}

// Per-time block: e^{i m phi_t} table, contract with S, normalize, ground mix.
__global__ void vis_kernel(const float* __restrict__ times,
                           const float* __restrict__ fsky,
                           const float* __restrict__ tg,
                           float* __restrict__ out)
{
    const int t = blockIdx.x;
    __shared__ float phc[MMC], phs[MMC];
    float phi = SIDEREALF * times[t];
    for (int j = threadIdx.x; j < MMC; j += blockDim.x) {
        float s, c;
        sincosf((float)(j - LMAXC) * phi, &s, &c);
        phc[j] = c; phs[j] = s;
    }
    __syncthreads();
    int f = threadIdx.x;
    if (f < FC) {
        float acc = 0.0f;
        #pragma unroll 4
        for (int j = 0; j < MMC; j++) {
            acc += phc[j] * g_S[j * NCC + 2 * f]
                 - phs[j] * g_S[j * NCC + 2 * f + 1];
        }
        float v  = acc / g_norm[f];
        float fs = fsky[f];
        out[t * FC + f] = fs * v + (1.0f - fs) * 300.0f * tg[0];
    }
}

extern "C" void kernel_launch(void* const* d_in, const int* in_sizes, int n_in,
                              void* d_out, int out_size)
{
    const float* br    = (const float*)d_in[0];
    const float* bi    = (const float*)d_in[1];
    const float* sr    = (const float*)d_in[2];
    const float* si    = (const float*)d_in[3];
    const float* dl    = (const float*)d_in[4];
    const float* euler = (const float*)d_in[5];
    const float* times = (const float*)d_in[6];
    const float* fsky  = (const float*)d_in[7];
    const float* tg    = (const float*)d_in[8];
    float* out = (float*)d_out;
    const int T = in_sizes[6];

    zero_S<<<(MMC * NCC + 255) / 256, 256>>>();

    dim3 grid((MMC + MT - 1) / MT, LC);
    conv_kernel<<<grid, NTHREADS>>>(br, bi, sr, si, dl, euler);

    vis_kernel<<<T, 128>>>(times, fsky, tg, out);
}

// round 6
// speedup vs baseline: 2.3369x; 1.4484x over previous
#include <cuda_runtime.h>
#include <cuda_bf16.h>
#include <math.h>

// Problem constants (fixed by setup_inputs)
#define LMAXC 180
#define LC    181           // L = lmax+1
#define MMC   361           // 2*lmax+1
#define FC    50            // n_freqs
#define NCC   100           // 2*F real columns (re/im interleaved)
#define MT    64            // m-tile per CTA
#define KC    32            // k per chunk (16 packed u32 cols)
#define AST   20            // A smem stride (u32) - conflict-free frag loads
#define BST   104           // B smem stride (u32) - conflict-free frag loads
#define NTHREADS 256
#define SIDEREALF 6.3003880989848976f
#define SQRT4PI   3.5449077018110318f

// Scratch (no allocations allowed)
__device__ float g_S[MMC * NCC];
__device__ float g_norm[FC];
__device__ float g_pgc[MMC], g_pgs[MMC];   // cos/sin(m*gamma)
__device__ float g_pac[MMC], g_pas[MMC];   // cos/sin(m*alpha)

__global__ void init_kernel(const float* __restrict__ euler) {
    int i = blockIdx.x * blockDim.x + threadIdx.x;
    if (i < MMC * NCC) g_S[i] = 0.0f;
    if (i < MMC) {
        float mf = (float)(i - LMAXC);
        float s, c;
        sincosf(mf * euler[2], &s, &c); g_pgc[i] = c; g_pgs[i] = s;
        sincosf(mf * euler[0], &s, &c); g_pac[i] = c; g_pas[i] = s;
    }
}

// bf16 split: v ~= hi + lo
__device__ __forceinline__ void split_bf16(float v, __nv_bfloat16& h, __nv_bfloat16& lo) {
    h  = __float2bfloat16(v);                    // rn
    lo = __float2bfloat16(v - __bfloat162float(h));
}
__device__ __forceinline__ unsigned pack2(__nv_bfloat16 k0, __nv_bfloat16 k1) {
    return ((unsigned)__bfloat16_as_ushort(k1) << 16) | (unsigned)__bfloat16_as_ushort(k0);
}

__device__ __forceinline__ void mma_bf16(float* c,
    unsigned a0, unsigned a1, unsigned a2, unsigned a3,
    unsigned b0, unsigned b1)
{
    asm volatile(
        "mma.sync.aligned.m16n8k16.row.col.f32.bf16.bf16.f32 "
        "{%0,%1,%2,%3}, {%4,%5,%6,%7}, {%8,%9}, {%0,%1,%2,%3};"
        : "+f"(c[0]), "+f"(c[1]), "+f"(c[2]), "+f"(c[3])
        : "r"(a0), "r"(a1), "r"(a2), "r"(a3), "r"(b0), "r"(b1));
}

// Per (m-tile, l) CTA: tensor-core banded GEMM, bf16 3-term split
//   D[m, 2f] = sum_n dl[l,m,n] * conj(beam[f,l,n] * pg[n])
// epilogue: S[m,f] += conj(pa[m]) * D[m,f] * sky[f,l,m]; l==0 writes norm.
__global__ void __launch_bounds__(NTHREADS) conv_kernel(
    const float* __restrict__ br_g, const float* __restrict__ bi_g,
    const float* __restrict__ sr_g, const float* __restrict__ si_g,
    const float* __restrict__ dl_g)
{
    const int l  = blockIdx.y;
    const int j0 = LMAXC - l, j1 = LMAXC + l;
    const int ntiles = (2 * l + 1 + MT - 1) / MT;
    const int mt = blockIdx.x;
    if (mt >= ntiles) return;
    const int jm0 = j0 + mt * MT;

    __shared__ unsigned Ah[MT][AST], Al[MT][AST];   // dl tile hi/lo (k-pairs packed)
    __shared__ unsigned Bh[16][BST], Bl[16][BST];   // conj(beam*pg) hi/lo

    const int tid  = threadIdx.x;
    const int lane = tid & 31;
    const int warp = tid >> 5;
    const int mstrip = warp & 3;          // 4 strips of 16 m-rows
    const int nhalf  = warp >> 2;         // 0 -> n-tiles 0..6, 1 -> 7..12
    const int ntile0  = nhalf ? 7 : 0;
    const int ntcount = nhalf ? 6 : 7;
    const int g  = lane >> 2;
    const int t4 = lane & 3;

    float acc[7][4];
    #pragma unroll
    for (int t = 0; t < 7; t++)
        #pragma unroll
        for (int q = 0; q < 4; q++) acc[t][q] = 0.0f;

    for (int k0 = j0; k0 <= j1; k0 += KC) {
        const int kmax = min(KC, j1 - k0 + 1);
        const int nks  = (kmax > 16) ? 2 : 1;

        // ---- stage A: dl rows jm0..jm0+63, k-pairs packed, bf16 hi/lo ----
        for (int i = tid; i < MT * 16; i += NTHREADS) {
            int pc = i & 15, rr = i >> 4;
            int jj = jm0 + rr;
            int n0 = k0 + 2 * pc;
            float v0 = 0.0f, v1 = 0.0f;
            if (jj <= j1) {
                const float* row = dl_g + ((size_t)l * MMC + jj) * MMC;
                if (n0     <= j1) v0 = row[n0];
                if (n0 + 1 <= j1) v1 = row[n0 + 1];
            }
            __nv_bfloat16 h0, l0, h1, l1;
            split_bf16(v0, h0, l0); split_bf16(v1, h1, l1);
            Ah[rr][pc] = pack2(h0, h1);
            Al[rr][pc] = pack2(l0, l1);
        }
        // ---- stage B: conj(beam*pg), re/im columns, bf16 hi/lo ----
        for (int i = tid; i < 16 * 52; i += NTHREADS) {
            int kp = i & 15, f = i >> 4;
            int n0 = k0 + 2 * kp;
            float br0 = 0.f, bi0 = 0.f, br1 = 0.f, bi1 = 0.f;
            if (f < FC) {
                size_t off = ((size_t)f * LC + l) * MMC;
                if (n0     <= j1) { br0 = br_g[off + n0];     bi0 = bi_g[off + n0];     }
                if (n0 + 1 <= j1) { br1 = br_g[off + n0 + 1]; bi1 = bi_g[off + n0 + 1]; }
            }
            int i0 = min(n0, 2 * LMAXC), i1 = min(n0 + 1, 2 * LMAXC);
            float c0 = g_pgc[i0], s0 = g_pgs[i0];
            float c1 = g_pgc[i1], s1 = g_pgs[i1];
            float re0 = br0 * c0 + bi0 * s0, im0 = br0 * s0 - bi0 * c0;
            float re1 = br1 * c1 + bi1 * s1, im1 = br1 * s1 - bi1 * c1;
            __nv_bfloat16 rh0, rl0, rh1, rl1, ih0, il0, ih1, il1;
            split_bf16(re0, rh0, rl0); split_bf16(re1, rh1, rl1);
            split_bf16(im0, ih0, il0); split_bf16(im1, ih1, il1);
            int col = 2 * f;              // f=50,51 land in pad cols 100..103 (zeros)
            Bh[kp][col]     = pack2(rh0, rh1);
            Bl[kp][col]     = pack2(rl0, rl1);
            Bh[kp][col + 1] = pack2(ih0, ih1);
            Bl[kp][col + 1] = pack2(il0, il1);
        }
        __syncthreads();

        // ---- MMA: nks k-steps of 16 ----
        #pragma unroll
        for (int ks = 0; ks < 2; ks++) {
            if (ks < nks) {
                const int ar = mstrip * 16 + g;
                const int ac = ks * 8 + t4;
                unsigned a0h = Ah[ar][ac],     a1h = Ah[ar + 8][ac];
                unsigned a2h = Ah[ar][ac + 4], a3h = Ah[ar + 8][ac + 4];
                unsigned a0l = Al[ar][ac],     a1l = Al[ar + 8][ac];
                unsigned a2l = Al[ar][ac + 4], a3l = Al[ar + 8][ac + 4];
                const int bk = ks * 8 + t4;
                #pragma unroll
                for (int t = 0; t < 7; t++) {
                    if (t < ntcount) {
                        int n0 = (ntile0 + t) * 8;
                        unsigned b0h = Bh[bk][n0 + g], b1h = Bh[bk + 4][n0 + g];
                        unsigned b0l = Bl[bk][n0 + g], b1l = Bl[bk + 4][n0 + g];
                        mma_bf16(acc[t], a0h, a1h, a2h, a3h, b0h, b1h);
                        mma_bf16(acc[t], a0h, a1h, a2h, a3h, b0l, b1l);
                        mma_bf16(acc[t], a0l, a1l, a2l, a3l, b0h, b1h);
                    }
                }
            }
        }
        __syncthreads();   // protect smem before next chunk's writes
    }

    // ---- epilogue: S[m,f] += conj(pa[m]) * D * sky ----
    const int r0 = jm0 + mstrip * 16 + g;
    const int r1 = r0 + 8;
    const int r0c = min(r0, 2 * LMAXC), r1c = min(r1, 2 * LMAXC);
    const float ca0 = g_pac[r0c], sa0 = g_pas[r0c];
    const float ca1 = g_pac[r1c], sa1 = g_pas[r1c];
    const bool v0 = (r0 <= j1);
    const bool v1 = (r1 <= j1);

    #pragma unroll
    for (int t = 0; t < 7; t++) {
        if (t < ntcount) {
            int f = 4 * (ntile0 + t) + t4;
            if (f < FC) {
                if (v0) {
                    float dre = acc[t][0], dim = acc[t][1];
                    float z1r = ca0 * dre - sa0 * dim;
                    float z1i = ca0 * dim + sa0 * dre;
                    size_t soff = ((size_t)f * LC + l) * MMC + r0;
                    float skr = sr_g[soff], ski = si_g[soff];
                    atomicAdd(&g_S[r0 * NCC + 2 * f],     z1r * skr - z1i * ski);
                    atomicAdd(&g_S[r0 * NCC + 2 * f + 1], z1r * ski + z1i * skr);
                }
                if (v1) {
                    float dre = acc[t][2], dim = acc[t][3];
                    float z1r = ca1 * dre - sa1 * dim;
                    float z1i = ca1 * dim + sa1 * dre;
                    size_t soff = ((size_t)f * LC + l) * MMC + r1;
                    float skr = sr_g[soff], ski = si_g[soff];
                    atomicAdd(&g_S[r1 * NCC + 2 * f],     z1r * skr - z1i * ski);
                    atomicAdd(&g_S[r1 * NCC + 2 * f + 1], z1r * ski + z1i * skr);
                }
                if (l == 0 && mstrip == 0 && g == 0) {
                    // r0 == LMAXC, pa = 1: norm = sqrt(4pi) * Re(D)
                    g_norm[f] = SQRT4PI * acc[t][0];
                }
            }
        }
    }
}

// Per-time block: e^{i m phi_t} table, contract with S, normalize, ground mix.
__global__ void vis_kernel(const float* __restrict__ times,
                           const float* __restrict__ fsky,
                           const float* __restrict__ tg,
                           float* __restrict__ out)
{
    const int t = blockIdx.x;
    __shared__ float phc[MMC], phs[MMC];
    float phi = SIDEREALF * times[t];
    for (int j = threadIdx.x; j < MMC; j += blockDim.x) {
        float s, c;
        sincosf((float)(j - LMAXC) * phi, &s, &c);
        phc[j] = c; phs[j] = s;
    }
    __syncthreads();
    int f = threadIdx.x;
    if (f < FC) {
        float acc = 0.0f;
        #pragma unroll 4
        for (int j = 0; j < MMC; j++) {
            acc += phc[j] * g_S[j * NCC + 2 * f]
                 - phs[j] * g_S[j * NCC + 2 * f + 1];
        }
        float v  = acc / g_norm[f];
        float fs = fsky[f];
        out[t * FC + f] = fs * v + (1.0f - fs) * 300.0f * tg[0];
    }
}

extern "C" void kernel_launch(void* const* d_in, const int* in_sizes, int n_in,
                              void* d_out, int out_size)
{
    const float* br    = (const float*)d_in[0];
    const float* bi    = (const float*)d_in[1];
    const float* sr    = (const float*)d_in[2];
    const float* si    = (const float*)d_in[3];
    const float* dl    = (const float*)d_in[4];
    const float* euler = (const float*)d_in[5];
    const float* times = (const float*)d_in[6];
    const float* fsky  = (const float*)d_in[7];
    const float* tg    = (const float*)d_in[8];
    float* out = (float*)d_out;
    const int T = in_sizes[6];

    init_kernel<<<(MMC * NCC + 255) / 256, 256>>>(euler);

    dim3 grid((MMC + MT - 1) / MT, LC);
    conv_kernel<<<grid, NTHREADS>>>(br, bi, sr, si, dl);

    vis_kernel<<<T, 128>>>(times, fsky, tg, out);
}

// round 7
// speedup vs baseline: 2.8830x; 1.2337x over previous
#include <cuda_runtime.h>
#include <cuda_fp16.h>
#include <math.h>

// Problem constants (fixed by setup_inputs)
#define LMAXC 180
#define LC    181           // L = lmax+1
#define MMC   361           // 2*lmax+1
#define FC    50            // n_freqs
#define NCC   100           // 2*F real columns (re/im interleaved)
#define MT    64            // m-tile per CTA
#define KC    32            // k per chunk (16 packed u32 k-pairs)
#define AST   20            // A smem stride (u32) - conflict-free
#define BST   104           // B smem stride (u32) - conflict-free
#define NTHREADS 256
#define SIDEREALF 6.3003880989848976f
#define SQRT4PI   3.5449077018110318f

// Scratch (no allocations allowed)
__device__ float  g_S[MMC * NCC];
__device__ float  g_norm[FC];
__device__ float2 g_pg2[MMC];   // (cos, sin)(m*gamma)
__device__ float2 g_pa2[MMC];   // (cos, sin)(m*alpha)

__global__ void init_kernel(const float* __restrict__ euler) {
    int i = blockIdx.x * blockDim.x + threadIdx.x;
    if (i < MMC * NCC) g_S[i] = 0.0f;
    if (i < MMC) {
        float mf = (float)(i - LMAXC);
        float s, c;
        sincosf(mf * euler[2], &s, &c); g_pg2[i] = make_float2(c, s);
        sincosf(mf * euler[0], &s, &c); g_pa2[i] = make_float2(c, s);
    }
}

__device__ __forceinline__ unsigned packh2(__half a, __half b) {
    return ((unsigned)__half_as_ushort(b) << 16) | (unsigned)__half_as_ushort(a);
}

__device__ __forceinline__ void mma_f16(float* c,
    unsigned a0, unsigned a1, unsigned a2, unsigned a3,
    unsigned b0, unsigned b1)
{
    asm volatile(
        "mma.sync.aligned.m16n8k16.row.col.f32.f16.f16.f32 "
        "{%0,%1,%2,%3}, {%4,%5,%6,%7}, {%8,%9}, {%0,%1,%2,%3};"
        : "+f"(c[0]), "+f"(c[1]), "+f"(c[2]), "+f"(c[3])
        : "r"(a0), "r"(a1), "r"(a2), "r"(a3), "r"(b0), "r"(b1));
}

// Stage one k-chunk into smem buffers (A: fp16 hi only; B: fp16 hi+lo)
__device__ __forceinline__ void stage_chunk(
    unsigned (*ah)[AST], unsigned (*bh)[BST], unsigned (*bl)[BST],
    const float* __restrict__ dl_g,
    const float* __restrict__ br_g, const float* __restrict__ bi_g,
    int l, int jm0, int j1, int k0, int tid)
{
    // ---- A: dl rows jm0..jm0+63, 16 packed k-pairs ----
    #pragma unroll
    for (int it = 0; it < 4; it++) {
        int i = tid + it * NTHREADS;           // 1024 total
        int pc = i & 15, rr = i >> 4;
        int jj = min(jm0 + rr, j1);            // rows past band: clamped (masked by epilogue)
        const float* row = dl_g + ((size_t)l * MMC + jj) * MMC;
        int n0 = k0 + 2 * pc;
        float v0 = row[min(n0,     2 * LMAXC)];  // cols past band: garbage x B(=0)
        float v1 = row[min(n0 + 1, 2 * LMAXC)];
        ah[rr][pc] = packh2(__float2half_rn(v0), __float2half_rn(v1));
    }
    // ---- B: conj(beam*pg), re/im columns, fp16 hi/lo ----
    #pragma unroll
    for (int it = 0; it < 4; it++) {
        int i = tid + it * NTHREADS;           // 832 total
        if (i < 16 * 52) {
            int kp = i & 15, f = i >> 4;
            int n0 = k0 + 2 * kp;
            float br0 = 0.f, bi0 = 0.f, br1 = 0.f, bi1 = 0.f;
            if (f < FC) {
                size_t off = ((size_t)f * LC + l) * MMC;
                if (n0     <= j1) { br0 = br_g[off + n0];     bi0 = bi_g[off + n0];     }
                if (n0 + 1 <= j1) { br1 = br_g[off + n0 + 1]; bi1 = bi_g[off + n0 + 1]; }
            }
            float2 p0 = g_pg2[min(n0,     2 * LMAXC)];
            float2 p1 = g_pg2[min(n0 + 1, 2 * LMAXC)];
            float re0 = br0 * p0.x + bi0 * p0.y, im0 = br0 * p0.y - bi0 * p0.x;
            float re1 = br1 * p1.x + bi1 * p1.y, im1 = br1 * p1.y - bi1 * p1.x;
            __half rh0 = __float2half_rn(re0), rh1 = __float2half_rn(re1);
            __half ih0 = __float2half_rn(im0), ih1 = __float2half_rn(im1);
            __half rl0 = __float2half_rn(re0 - __half2float(rh0));
            __half rl1 = __float2half_rn(re1 - __half2float(rh1));
            __half il0 = __float2half_rn(im0 - __half2float(ih0));
            __half il1 = __float2half_rn(im1 - __half2float(ih1));
            int col = 2 * f;                   // f=50,51 -> pad cols 100..103 (zeros)
            bh[kp][col]     = packh2(rh0, rh1);
            bl[kp][col]     = packh2(rl0, rl1);
            bh[kp][col + 1] = packh2(ih0, ih1);
            bl[kp][col + 1] = packh2(il0, il1);
        }
    }
}

// Per (m-tile, l) CTA: fp16 2-term split tensor-core banded GEMM
//   D[m, 2f] = sum_n dl[l,m,n] * conj(beam[f,l,n] * pg[n])
// epilogue: S[m,f] += conj(pa[m]) * D[m,f] * sky[f,l,m]; l==0 writes norm.
__global__ void __launch_bounds__(NTHREADS) conv_kernel(
    const float* __restrict__ br_g, const float* __restrict__ bi_g,
    const float* __restrict__ sr_g, const float* __restrict__ si_g,
    const float* __restrict__ dl_g)
{
    const int l  = (LC - 1) - blockIdx.y;       // heavy CTAs first
    const int j0 = LMAXC - l, j1 = LMAXC + l;
    const int ntiles_m = (2 * l + 1 + MT - 1) / MT;
    const int mt = blockIdx.x;
    if (mt >= ntiles_m) return;
    const int jm0 = j0 + mt * MT;

    __shared__ unsigned Ah[2][MT][AST];          // 10240 B
    __shared__ unsigned Bh[2][16][BST];          // 13312 B
    __shared__ unsigned Bl[2][16][BST];          // 13312 B

    const int tid   = threadIdx.x;
    const int lane  = tid & 31;
    const int warp  = tid >> 5;
    const int mhalf = warp & 1;                  // 0/1: m-rows [0,32) / [32,64)
    const int ngrp  = warp >> 1;                 // 0..3 n-groups
    const int tbase = (ngrp == 0) ? 0 : 4 + 3 * (ngrp - 1);   // 0,4,7,10
    const int tcnt  = (ngrp == 0) ? 4 : 3;
    const int g  = lane >> 2;
    const int t4 = lane & 3;

    float acc[2][4][4];
    #pragma unroll
    for (int a = 0; a < 2; a++)
        #pragma unroll
        for (int t = 0; t < 4; t++)
            #pragma unroll
            for (int q = 0; q < 4; q++) acc[a][t][q] = 0.0f;

    const int nch = (2 * l + 1 + KC - 1) / KC;

    stage_chunk(Ah[0], Bh[0], Bl[0], dl_g, br_g, bi_g, l, jm0, j1, j0, tid);
    __syncthreads();

    for (int c = 0; c < nch; c++) {
        if (c + 1 < nch)
            stage_chunk(Ah[(c + 1) & 1], Bh[(c + 1) & 1], Bl[(c + 1) & 1],
                        dl_g, br_g, bi_g, l, jm0, j1, j0 + (c + 1) * KC, tid);

        const unsigned (*ah)[AST] = Ah[c & 1];
        const unsigned (*bhp)[BST] = Bh[c & 1];
        const unsigned (*blp)[BST] = Bl[c & 1];
        const int k0 = j0 + c * KC;
        const int nks = (j1 - k0 + 1 > 16) ? 2 : 1;

        #pragma unroll
        for (int ks = 0; ks < 2; ks++) {
            if (ks < nks) {
                const int ac = ks * 8 + t4;
                const int ar0 = mhalf * 32 + g;
                unsigned a00 = ah[ar0][ac],      a01 = ah[ar0 + 8][ac];
                unsigned a02 = ah[ar0][ac + 4],  a03 = ah[ar0 + 8][ac + 4];
                unsigned a10 = ah[ar0 + 16][ac],     a11 = ah[ar0 + 24][ac];
                unsigned a12 = ah[ar0 + 16][ac + 4], a13 = ah[ar0 + 24][ac + 4];
                const int bk = ks * 8 + t4;
                #pragma unroll
                for (int t = 0; t < 4; t++) {
                    if (t < tcnt) {
                        int n0 = (tbase + t) * 8;
                        unsigned b0h = bhp[bk][n0 + g], b1h = bhp[bk + 4][n0 + g];
                        unsigned b0l = blp[bk][n0 + g], b1l = blp[bk + 4][n0 + g];
                        mma_f16(acc[0][t], a00, a01, a02, a03, b0h, b1h);
                        mma_f16(acc[0][t], a00, a01, a02, a03, b0l, b1l);
                        mma_f16(acc[1][t], a10, a11, a12, a13, b0h, b1h);
                        mma_f16(acc[1][t], a10, a11, a12, a13, b0l, b1l);
                    }
                }
            }
        }
        __syncthreads();
    }

    // ---- epilogue: S[m,f] += conj(pa[m]) * D * sky ----
    #pragma unroll
    for (int mf = 0; mf < 2; mf++) {
        const int r0 = jm0 + mhalf * 32 + mf * 16 + g;
        const int r1 = r0 + 8;
        float2 pa0 = g_pa2[min(r0, 2 * LMAXC)];
        float2 pa1 = g_pa2[min(r1, 2 * LMAXC)];
        const bool v0 = (r0 <= j1);
        const bool v1 = (r1 <= j1);
        #pragma unroll
        for (int t = 0; t < 4; t++) {
            if (t < tcnt) {
                int f = 4 * (tbase + t) + t4;
                if (f < FC) {
                    if (v0) {
                        float dre = acc[mf][t][0], dim = acc[mf][t][1];
                        float z1r = pa0.x * dre - pa0.y * dim;
                        float z1i = pa0.x * dim + pa0.y * dre;
                        size_t soff = ((size_t)f * LC + l) * MMC + r0;
                        float skr = sr_g[soff], ski = si_g[soff];
                        atomicAdd(&g_S[r0 * NCC + 2 * f],     z1r * skr - z1i * ski);
                        atomicAdd(&g_S[r0 * NCC + 2 * f + 1], z1r * ski + z1i * skr);
                    }
                    if (v1) {
                        float dre = acc[mf][t][2], dim = acc[mf][t][3];
                        float z1r = pa1.x * dre - pa1.y * dim;
                        float z1i = pa1.x * dim + pa1.y * dre;
                        size_t soff = ((size_t)f * LC + l) * MMC + r1;
                        float skr = sr_g[soff], ski = si_g[soff];
                        atomicAdd(&g_S[r1 * NCC + 2 * f],     z1r * skr - z1i * ski);
                        atomicAdd(&g_S[r1 * NCC + 2 * f + 1], z1r * ski + z1i * skr);
                    }
                    if (l == 0 && mhalf == 0 && mf == 0 && g == 0) {
                        // r0 == LMAXC, pa = 1: norm = sqrt(4pi) * Re(D)
                        g_norm[f] = SQRT4PI * acc[0][t][0];
                    }
                }
            }
        }
    }
}

// Per-time block: e^{i m phi_t} table, contract with S, normalize, ground mix.
__global__ void vis_kernel(const float* __restrict__ times,
                           const float* __restrict__ fsky,
                           const float* __restrict__ tg,
                           float* __restrict__ out)
{
    const int t = blockIdx.x;
    __shared__ float phc[MMC], phs[MMC];
    float phi = SIDEREALF * times[t];
    for (int j = threadIdx.x; j < MMC; j += blockDim.x) {
        float s, c;
        sincosf((float)(j - LMAXC) * phi, &s, &c);
        phc[j] = c; phs[j] = s;
    }
    __syncthreads();
    int f = threadIdx.x;
    if (f < FC) {
        float acc = 0.0f;
        #pragma unroll 4
        for (int j = 0; j < MMC; j++) {
            acc += phc[j] * g_S[j * NCC + 2 * f]
                 - phs[j] * g_S[j * NCC + 2 * f + 1];
        }
        float v  = acc / g_norm[f];
        float fs = fsky[f];
        out[t * FC + f] = fs * v + (1.0f - fs) * 300.0f * tg[0];
    }
}

extern "C" void kernel_launch(void* const* d_in, const int* in_sizes, int n_in,
                              void* d_out, int out_size)
{
    const float* br    = (const float*)d_in[0];
    const float* bi    = (const float*)d_in[1];
    const float* sr    = (const float*)d_in[2];
    const float* si    = (const float*)d_in[3];
    const float* dl    = (const float*)d_in[4];
    const float* euler = (const float*)d_in[5];
    const float* times = (const float*)d_in[6];
    const float* fsky  = (const float*)d_in[7];
    const float* tg    = (const float*)d_in[8];
    float* out = (float*)d_out;
    const int T = in_sizes[6];

    init_kernel<<<(MMC * NCC + 255) / 256, 256>>>(euler);

    dim3 grid((MMC + MT - 1) / MT, LC);
    conv_kernel<<<grid, NTHREADS>>>(br, bi, sr, si, dl);

    vis_kernel<<<T, 128>>>(times, fsky, tg, out);
}